// round 14
// baseline (speedup 1.0000x reference)
#include <cuda_runtime.h>

// Problem constants (fixed by reference setup_inputs)
#define BB   4
#define NN   10
#define KK   5
#define QTOT 512
#define DD   1536
#define D4   (DD / 4)        // 384 float4 per row

#define CH   64              // query chunks per batch
#define QC   (QTOT / CH)     // 8 query rows per block
#define GRID (BB * CH)       // 256 blocks (single wave @ 2 blocks/SM on 148 SMs)
#define TPB  128

// Scratch (device globals; counters self-reset each run)
__device__ float    g_part[BB][CH][DD];  // per-chunk column sums of query
__device__ float    g_sq[BB][CH];        // per-chunk sum of squared query elems
__device__ unsigned g_bar1;              // grid barrier arrival counter
__device__ unsigned g_done;              // completion counter (for reset)

__global__ void __launch_bounds__(TPB, 2)
fused_kernel(const float* __restrict__ support,
             const float* __restrict__ query,
             float* __restrict__ out_agg,
             float* __restrict__ out_qgw)
{
    const int tid  = threadIdx.x;          // 0..127
    const int lane = tid & 31, warp = tid >> 5;
    const int bn   = blockIdx.x;           // phase-2 identity for blocks < BB*NN
    const bool is_p2 = (bn < BB * NN);

    __shared__ float sred[2 * KK][4];
    __shared__ float sw[KK];
    __shared__ float swsq[4];

    // ---- Prefetch support tile + compute ||s||^2 BEFORE phase 1 / barrier ----
    // (independent of query; hides support DRAM latency behind phase-1 work)
    float4 s0[KK], s1[KK], s2[KK];
    float sn[KK];
    if (is_p2) {
        const float* S = support + (size_t)bn * KK * DD;
        #pragma unroll
        for (int k = 0; k < KK; k++) {
            const float4* Sk = reinterpret_cast<const float4*>(S + k * DD);
            s0[k] = Sk[tid]; s1[k] = Sk[tid + 128]; s2[k] = Sk[tid + 256];
        }
        #pragma unroll
        for (int k = 0; k < KK; k++) {
            sn[k] = s0[k].x*s0[k].x + s0[k].y*s0[k].y + s0[k].z*s0[k].z + s0[k].w*s0[k].w
                  + s1[k].x*s1[k].x + s1[k].y*s1[k].y + s1[k].z*s1[k].z + s1[k].w*s1[k].w
                  + s2[k].x*s2[k].x + s2[k].y*s2[k].y + s2[k].z*s2[k].z + s2[k].w*s2[k].w;
        }
    }

    // ================= Phase 1: partial query reduction =================
    {
        const int b = blockIdx.x / CH;
        const int c = blockIdx.x % CH;
        const float4* qb = reinterpret_cast<const float4*>(query)
                         + (size_t)b * QTOT * D4 + (size_t)c * QC * D4;

        float4 acc0 = make_float4(0.f, 0.f, 0.f, 0.f);
        float4 acc1 = make_float4(0.f, 0.f, 0.f, 0.f);
        float4 acc2 = make_float4(0.f, 0.f, 0.f, 0.f);
        float sq = 0.0f;

        #pragma unroll
        for (int q = 0; q < QC; q++) {
            const float4* row = qb + (size_t)q * D4;
            float4 v0 = row[tid];
            float4 v1 = row[tid + 128];
            float4 v2 = row[tid + 256];
            acc0.x += v0.x; acc0.y += v0.y; acc0.z += v0.z; acc0.w += v0.w;
            acc1.x += v1.x; acc1.y += v1.y; acc1.z += v1.z; acc1.w += v1.w;
            acc2.x += v2.x; acc2.y += v2.y; acc2.z += v2.z; acc2.w += v2.w;
            sq += v0.x*v0.x + v0.y*v0.y + v0.z*v0.z + v0.w*v0.w;
            sq += v1.x*v1.x + v1.y*v1.y + v1.z*v1.z + v1.w*v1.w;
            sq += v2.x*v2.x + v2.y*v2.y + v2.z*v2.z + v2.w*v2.w;
        }

        float4* dst = reinterpret_cast<float4*>(&g_part[b][c][0]);
        dst[tid]       = acc0;      // coalesced
        dst[tid + 128] = acc1;
        dst[tid + 256] = acc2;

        #pragma unroll
        for (int off = 16; off > 0; off >>= 1)
            sq += __shfl_down_sync(0xFFFFFFFFu, sq, off);
        if (lane == 0) swsq[warp] = sq;
        __syncthreads();
        if (tid == 0)
            g_sq[blockIdx.x / CH][blockIdx.x % CH] = swsq[0] + swsq[1] + swsq[2] + swsq[3];
    }

    // ============== Grid barrier (release -> arrive -> spin -> acquire) =====
    __threadfence();              // publish partial stores
    __syncthreads();
    if (tid == 0) {
        atomicAdd(&g_bar1, 1u);
        while (*((volatile unsigned*)&g_bar1) < GRID) { __nanosleep(64); }
    }
    __syncthreads();
    __threadfence();              // acquire

    // ================= Phase 2: per-(b,n) weights + aggregation ============
    if (is_p2) {
        const int b = bn / NN;
        const float invQ = 1.0f / (float)QTOT;

        // q-bar (sum over queries) for this thread's 3 float4 columns (L2-hot)
        float4 qb0 = make_float4(0.f,0.f,0.f,0.f);
        float4 qb1 = make_float4(0.f,0.f,0.f,0.f);
        float4 qb2 = make_float4(0.f,0.f,0.f,0.f);
        const float4* pbase = reinterpret_cast<const float4*>(&g_part[b][0][0]);
        #pragma unroll 8
        for (int c = 0; c < CH; c++) {
            const float4* p = pbase + (size_t)c * D4;
            float4 v0 = p[tid], v1 = p[tid + 128], v2 = p[tid + 256];
            qb0.x += v0.x; qb0.y += v0.y; qb0.z += v0.z; qb0.w += v0.w;
            qb1.x += v1.x; qb1.y += v1.y; qb1.z += v1.z; qb1.w += v1.w;
            qb2.x += v2.x; qb2.y += v2.y; qb2.z += v2.z; qb2.w += v2.w;
        }

        // dots vs q-bar (support already in registers)
        float dot[KK];
        #pragma unroll
        for (int k = 0; k < KK; k++) {
            dot[k] = s0[k].x*qb0.x + s0[k].y*qb0.y + s0[k].z*qb0.z + s0[k].w*qb0.w
                   + s1[k].x*qb1.x + s1[k].y*qb1.y + s1[k].z*qb1.z + s1[k].w*qb1.w
                   + s2[k].x*qb2.x + s2[k].y*qb2.y + s2[k].z*qb2.z + s2[k].w*qb2.w;
        }

        // block reduction of 10 scalars
        #pragma unroll
        for (int k = 0; k < KK; k++) {
            float dv = dot[k], sv = sn[k];
            #pragma unroll
            for (int off = 16; off > 0; off >>= 1) {
                dv += __shfl_down_sync(0xFFFFFFFFu, dv, off);
                sv += __shfl_down_sync(0xFFFFFFFFu, sv, off);
            }
            if (lane == 0) { sred[k][warp] = dv; sred[KK + k][warp] = sv; }
        }
        __syncthreads();

        if (tid == 0) {
            float qn = 0.f;
            #pragma unroll
            for (int c = 0; c < CH; c++) qn += g_sq[b][c];
            qn *= invQ;                             // mean_q ||q||^2

            float t[KK], mx = -1e30f;
            #pragma unroll
            for (int k = 0; k < KK; k++) {
                float dsum = sred[k][0] + sred[k][1] + sred[k][2] + sred[k][3];
                float ssum = sred[KK+k][0] + sred[KK+k][1] + sred[KK+k][2] + sred[KK+k][3];
                float m = -(ssum - 2.0f * dsum * invQ + qn); // mean_q dist_sq
                t[k] = tanhf(m);
                mx = fmaxf(mx, t[k]);
            }
            float esum = 0.f;
            #pragma unroll
            for (int k = 0; k < KK; k++) { t[k] = __expf(t[k] - mx); esum += t[k]; }
            float inv = 1.0f / esum;
            #pragma unroll
            for (int k = 0; k < KK; k++) {
                float wk = t[k] * inv;
                sw[k] = wk;
                out_qgw[bn * KK + k] = wk;
            }
        }
        __syncthreads();

        float w0 = sw[0], w1 = sw[1], w2 = sw[2], w3 = sw[3], w4 = sw[4];
        float4* Oa = reinterpret_cast<float4*>(out_agg + (size_t)bn * DD);
        float4 a;
        a.x = s0[0].x*w0 + s0[1].x*w1 + s0[2].x*w2 + s0[3].x*w3 + s0[4].x*w4;
        a.y = s0[0].y*w0 + s0[1].y*w1 + s0[2].y*w2 + s0[3].y*w3 + s0[4].y*w4;
        a.z = s0[0].z*w0 + s0[1].z*w1 + s0[2].z*w2 + s0[3].z*w3 + s0[4].z*w4;
        a.w = s0[0].w*w0 + s0[1].w*w1 + s0[2].w*w2 + s0[3].w*w3 + s0[4].w*w4;
        Oa[tid] = a;
        a.x = s1[0].x*w0 + s1[1].x*w1 + s1[2].x*w2 + s1[3].x*w3 + s1[4].x*w4;
        a.y = s1[0].y*w0 + s1[1].y*w1 + s1[2].y*w2 + s1[3].y*w3 + s1[4].y*w4;
        a.z = s1[0].z*w0 + s1[1].z*w1 + s1[2].z*w2 + s1[3].z*w3 + s1[4].z*w4;
        a.w = s1[0].w*w0 + s1[1].w*w1 + s1[2].w*w2 + s1[3].w*w3 + s1[4].w*w4;
        Oa[tid + 128] = a;
        a.x = s2[0].x*w0 + s2[1].x*w1 + s2[2].x*w2 + s2[3].x*w3 + s2[4].x*w4;
        a.y = s2[0].y*w0 + s2[1].y*w1 + s2[2].y*w2 + s2[3].y*w3 + s2[4].y*w4;
        a.z = s2[0].z*w0 + s2[1].z*w1 + s2[2].z*w2 + s2[3].z*w3 + s2[4].z*w4;
        a.w = s2[0].w*w0 + s2[1].w*w1 + s2[2].w*w2 + s2[3].w*w3 + s2[4].w*w4;
        Oa[tid + 256] = a;
    }

    // ================= Reset counters for next graph replay =================
    if (tid == 0) {
        unsigned old = atomicAdd(&g_done, 1u);
        if (old == GRID - 1) {
            atomicExch(&g_bar1, 0u);
            atomicExch(&g_done, 0u);
        }
    }
}

extern "C" void kernel_launch(void* const* d_in, const int* in_sizes, int n_in,
                              void* d_out, int out_size) {
    const float* support = (const float*)d_in[0];
    const float* query   = (const float*)d_in[1];
    float* out = (float*)d_out;

    float* out_agg = out;                          // (B,N,D)
    float* out_qgw = out + (size_t)BB * NN * DD;   // (B,N,K,1)

    fused_kernel<<<GRID, TPB>>>(support, query, out_agg, out_qgw);
}